// round 9
// baseline (speedup 1.0000x reference)
#include <cuda_runtime.h>
#include <cuda_bf16.h>

#define NG 1024
#define HH 768
#define WW 768
#define TPX 16   // pixels per thread along w (8 f32x2 pairs)

// Per-gaussian coefficients, 16 floats (4 x float4):
// [0]=mx [1]=-my [2]=Dm [3]=Dm2 | [4]=A [5]=B [6]=D [7]=D(dup)
// [8]=s [9]=s3 [10]=s4 [11]=0   | [12]=wr [13]=wg [14]=wb [15]=0
// A,B,D pre-scaled by -0.5*log2(e); s = 2^(2*D*delta^2)
__device__ __align__(16) float g_coef[NG * 16];

typedef unsigned long long u64;

__device__ __forceinline__ u64 pk2(float lo, float hi) {
    u64 d; asm("mov.b64 %0, {%1, %2};" : "=l"(d) : "f"(lo), "f"(hi)); return d;
}
__device__ __forceinline__ void upk2(u64 v, float& lo, float& hi) {
    asm("mov.b64 {%0, %1}, %2;" : "=f"(lo), "=f"(hi) : "l"(v));
}
__device__ __forceinline__ u64 fma2(u64 a, u64 b, u64 c) {
    u64 d; asm("fma.rn.f32x2 %0, %1, %2, %3;" : "=l"(d) : "l"(a), "l"(b), "l"(c)); return d;
}
__device__ __forceinline__ u64 mul2(u64 a, u64 b) {
    u64 d; asm("mul.rn.f32x2 %0, %1, %2;" : "=l"(d) : "l"(a), "l"(b)); return d;
}
__device__ __forceinline__ float ex2f(float a) {
    float v; asm("ex2.approx.ftz.f32 %0, %1;" : "=f"(v) : "f"(a)); return v;
}

__global__ void prep_kernel(const float* __restrict__ means,
                            const float* __restrict__ cov,
                            const float* __restrict__ colors) {
    int n = blockIdx.x * blockDim.x + threadIdx.x;
    if (n >= NG) return;
    float mx = means[2 * n + 0];
    float my = means[2 * n + 1];
    float a = cov[4 * n + 0];
    float b = cov[4 * n + 1];
    float c = cov[4 * n + 2];
    float d = cov[4 * n + 3];
    float det = a * d - b * c;
    float ia  = d / det;
    float ibc = (-b - c) / det;   // ib + ic
    float idd = a / det;
    const float k = -0.72134752044448170368f;  // -0.5 * log2(e)
    float A = k * ia;
    float B = k * ibc;
    float D = k * idd;
    float Dm  = -2.0f * D * my;
    float Dm2 = D * my * my;
    const float delta = 1.0f / 767.0f;
    float s  = exp2f(2.0f * D * delta * delta);
    float s3 = s * s * s;
    float s4 = s * s3;
    float cr = colors[4 * n + 0];
    float cg = colors[4 * n + 1];
    float cb = colors[4 * n + 2];
    float al = colors[4 * n + 3];
    float wr = al / (1.0f + __expf(-cr));
    float wg = al / (1.0f + __expf(-cg));
    float wb = al / (1.0f + __expf(-cb));
    float* o = g_coef + 16 * n;
    o[0]  = mx; o[1]  = -my; o[2]  = Dm; o[3]  = Dm2;
    o[4]  = A;  o[5]  = B;   o[6]  = D;  o[7]  = D;
    o[8]  = s;  o[9]  = s3;  o[10] = s4; o[11] = 0.f;
    o[12] = wr; o[13] = wg;  o[14] = wb; o[15] = 0.f;
}

// Block: 128 threads = 8 segments (16 px each, 128 px wide) x 16 rows.
// Grid (768/128, 768/16) = (6, 48) = 288 blocks. Dynamic smem 64KB.
__global__ __launch_bounds__(128)
void render_kernel(float* __restrict__ out) {
    extern __shared__ float shf[];          // 64 KB, 16 floats per gaussian
    u64* shu = (u64*)shf;
    {
        const float4* gc = (const float4*)g_coef;
        float4* sf = (float4*)shf;
        #pragma unroll 8
        for (int i = threadIdx.x; i < NG * 4; i += 128) sf[i] = gc[i];
    }
    __syncthreads();

    int tid = threadIdx.x;
    int seg = tid & 7;     // 0..7 -> which 16-pixel segment
    int row = tid >> 3;    // 0..15 -> row within tile
    int h  = blockIdx.y * 16 + row;
    int w0 = blockIdx.x * 128 + seg * TPX;

    const float inv = 1.0f / 767.0f;   // delta
    float x  = (float)h * inv;
    float y0 = (float)w0 * inv;
    float y0sq = y0 * y0;
    float K2   = inv * (2.0f * y0 + inv);   // delta*(2*y0+delta)
    u64 yK  = pk2(y0sq, K2);                // multiplicand for {t0,t1}
    u64 y0d = pk2(y0, inv);                 // multiplicand for {arg0,rarg}

    u64 ar2[TPX / 2], ag2[TPX / 2], ab2[TPX / 2];
    #pragma unroll
    for (int kk = 0; kk < TPX / 2; kk++) { ar2[kk] = 0ull; ag2[kk] = 0ull; ab2[kk] = 0ull; }

    #pragma unroll 4
    for (int n = 0; n < NG; n++) {
        const float4* q = (const float4*)(shf + 16 * n);
        float4 q0 = q[0];                   // mx, -my, Dm, Dm2
        u64 AB = shu[8 * n + 2];            // {A, B}
        u64 DD = shu[8 * n + 3];            // {D, D}
        u64 sp = shu[8 * n + 4];            // {s, s^3}
        float s4 = shf[16 * n + 10];
        float4 q3 = q[3];                   // wr, wg, wb, 0
        float mx = q0.x, nmy = q0.y, Dm = q0.z, Dm2 = q0.w;

        // Hoist per (gaussian, row): arg(y) = e0 + e1*y + D*y^2
        float dx = x - mx;
        u64 tc = mul2(AB, pk2(dx, dx));     // {A*dx, B*dx}
        float t, c1;
        upk2(tc, t, c1);
        float c0 = fmaf(t, dx, Dm2);
        float e1 = c1 + Dm;
        float e0 = fmaf(nmy, c1, c0);

        // {arg0, rarg} = {e1,e1} * {y0,delta} + ({D,D} * {y0^2, K2} + {e0, 0})
        u64 t01  = fma2(DD, yK, pk2(e0, 0.0f));
        u64 ar01 = fma2(pk2(e1, e1), y0d, t01);
        float a0, rr;
        upk2(ar01, a0, rr);
        float v0 = ex2f(a0);
        float r0 = ex2f(rr);

        // {v1, r0^2} = {v0, r0} * {r0, r0}
        u64 vr = mul2(pk2(v0, r0), pk2(r0, r0));
        float v1, r0q;
        upk2(vr, v1, r0q);
        u64 V  = pk2(v0, v1);
        u64 P  = mul2(pk2(r0q, r0q), sp);   // {r0^2*s, r0^2*s^3}
        u64 S4 = pk2(s4, s4);

        u64 wr2 = pk2(q3.x, q3.x);
        u64 wg2 = pk2(q3.y, q3.y);
        u64 wb2 = pk2(q3.z, q3.z);

        #pragma unroll
        for (int kk = 0; kk < TPX / 2; kk++) {
            ar2[kk] = fma2(V, wr2, ar2[kk]);
            ag2[kk] = fma2(V, wg2, ag2[kk]);
            ab2[kk] = fma2(V, wb2, ab2[kk]);
            if (kk < TPX / 2 - 1) {
                V = mul2(V, P);
                if (kk < TPX / 2 - 2) P = mul2(P, S4);
            }
        }
    }

    // Unpack and store: 48 contiguous floats per thread -> 12 x STG.128
    float r[TPX], g[TPX], b[TPX];
    #pragma unroll
    for (int kk = 0; kk < TPX / 2; kk++) {
        upk2(ar2[kk], r[2 * kk], r[2 * kk + 1]);
        upk2(ag2[kk], g[2 * kk], g[2 * kk + 1]);
        upk2(ab2[kk], b[2 * kk], b[2 * kk + 1]);
    }
    float buf[TPX * 3];
    #pragma unroll
    for (int j = 0; j < TPX; j++) {
        buf[3 * j + 0] = r[j];
        buf[3 * j + 1] = g[j];
        buf[3 * j + 2] = b[j];
    }
    float4* o = (float4*)(out + ((size_t)h * WW + w0) * 3);
    #pragma unroll
    for (int q = 0; q < TPX * 3 / 4; q++) o[q] = ((float4*)buf)[q];
}

extern "C" void kernel_launch(void* const* d_in, const int* in_sizes, int n_in,
                              void* d_out, int out_size) {
    const float* means  = (const float*)d_in[0];
    const float* cov    = (const float*)d_in[1];
    const float* colors = (const float*)d_in[2];
    float* out = (float*)d_out;

    static int configured = 0;
    if (!configured) {
        cudaFuncSetAttribute(render_kernel,
                             cudaFuncAttributeMaxDynamicSharedMemorySize, NG * 16 * 4);
        configured = 1;
    }

    prep_kernel<<<4, 256>>>(means, cov, colors);
    dim3 grid(WW / 128, HH / 16);
    render_kernel<<<grid, 128, NG * 16 * 4>>>(out);
}

// round 10
// speedup vs baseline: 1.1345x; 1.1345x over previous
#include <cuda_runtime.h>
#include <cuda_bf16.h>

#define NG 1024
#define HH 768
#define WW 768
#define TPX 32   // pixels per thread along w (16 f32x2 pairs)

// Per-gaussian coefficients, 16 floats (4 x float4):
// q0: [0]=mx [1]=-my [2]=Dm [3]=Dm2
// q1: [4]=A  [5]=B   [6]=D  [7]=s4
// q2: [8]=s  [9]=s3  [10]=wr [11]=wg
// q3: [12]=wb [13..15]=pad
// A,B,D pre-scaled by -0.5*log2(e); s = 2^(2*D*delta^2)
__device__ __align__(16) float g_coef[NG * 16];

typedef unsigned long long u64;

__device__ __forceinline__ u64 pk2(float lo, float hi) {
    u64 d; asm("mov.b64 %0, {%1, %2};" : "=l"(d) : "f"(lo), "f"(hi)); return d;
}
__device__ __forceinline__ void upk2(u64 v, float& lo, float& hi) {
    asm("mov.b64 {%0, %1}, %2;" : "=f"(lo), "=f"(hi) : "l"(v));
}
__device__ __forceinline__ u64 fma2(u64 a, u64 b, u64 c) {
    u64 d; asm("fma.rn.f32x2 %0, %1, %2, %3;" : "=l"(d) : "l"(a), "l"(b), "l"(c)); return d;
}
__device__ __forceinline__ u64 mul2(u64 a, u64 b) {
    u64 d; asm("mul.rn.f32x2 %0, %1, %2;" : "=l"(d) : "l"(a), "l"(b)); return d;
}
__device__ __forceinline__ float ex2f(float a) {
    float v; asm("ex2.approx.ftz.f32 %0, %1;" : "=f"(v) : "f"(a)); return v;
}

__global__ void prep_kernel(const float* __restrict__ means,
                            const float* __restrict__ cov,
                            const float* __restrict__ colors) {
    int n = blockIdx.x * blockDim.x + threadIdx.x;
    if (n >= NG) return;
    float mx = means[2 * n + 0];
    float my = means[2 * n + 1];
    float a = cov[4 * n + 0];
    float b = cov[4 * n + 1];
    float c = cov[4 * n + 2];
    float d = cov[4 * n + 3];
    float det = a * d - b * c;
    float ia  = d / det;
    float ibc = (-b - c) / det;   // ib + ic
    float idd = a / det;
    const float k = -0.72134752044448170368f;  // -0.5 * log2(e)
    float A = k * ia;
    float B = k * ibc;
    float D = k * idd;
    float Dm  = -2.0f * D * my;
    float Dm2 = D * my * my;
    const float delta = 1.0f / 767.0f;
    float s  = exp2f(2.0f * D * delta * delta);
    float s3 = s * s * s;
    float s4 = s * s3;
    float cr = colors[4 * n + 0];
    float cg = colors[4 * n + 1];
    float cb = colors[4 * n + 2];
    float al = colors[4 * n + 3];
    float wr = al / (1.0f + __expf(-cr));
    float wg = al / (1.0f + __expf(-cg));
    float wb = al / (1.0f + __expf(-cb));
    float* o = g_coef + 16 * n;
    o[0]  = mx; o[1]  = -my; o[2]  = Dm; o[3]  = Dm2;
    o[4]  = A;  o[5]  = B;   o[6]  = D;  o[7]  = s4;
    o[8]  = s;  o[9]  = s3;  o[10] = wr; o[11] = wg;
    o[12] = wb; o[13] = 0.f; o[14] = 0.f; o[15] = 0.f;
}

// Block: 64 threads = 4 segments (32 px each, 128 px wide) x 16 rows.
// Grid (768/128, 768/16) = (6, 48) = 288 blocks, 2 CTAs/SM. Dynamic smem 64KB.
__global__ __launch_bounds__(64)
void render_kernel(float* __restrict__ out) {
    extern __shared__ float shf[];          // 64 KB, 16 floats per gaussian
    {
        const float4* gc = (const float4*)g_coef;
        float4* sf = (float4*)shf;
        #pragma unroll 8
        for (int i = threadIdx.x; i < NG * 4; i += 64) sf[i] = gc[i];
    }
    __syncthreads();

    int tid = threadIdx.x;
    int seg = tid & 3;     // 0..3 -> which 32-pixel segment
    int row = tid >> 2;    // 0..15 -> row within tile
    int h  = blockIdx.y * 16 + row;
    int w0 = blockIdx.x * 128 + seg * TPX;

    const float inv = 1.0f / 767.0f;   // delta
    float x  = (float)h * inv;
    float y0 = (float)w0 * inv;
    float y0sq  = y0 * y0;
    float c2y0d = 2.0f * y0 + inv;     // (2*y0 + delta), for r0 arg

    u64 ar2[TPX / 2], ag2[TPX / 2], ab2[TPX / 2];
    #pragma unroll
    for (int kk = 0; kk < TPX / 2; kk++) { ar2[kk] = 0ull; ag2[kk] = 0ull; ab2[kk] = 0ull; }

    #pragma unroll 2
    for (int n = 0; n < NG; n++) {
        const float4* q = (const float4*)(shf + 16 * n);
        float4 q0 = q[0];   // mx, -my, Dm, Dm2
        float4 q1 = q[1];   // A, B, D, s4
        float4 q2 = q[2];   // s, s3, wr, wg
        float wb = shf[16 * n + 12];
        float mx = q0.x, nmy = q0.y, Dm = q0.z, Dm2 = q0.w;
        float A  = q1.x, B   = q1.y, D  = q1.z, s4  = q1.w;

        // Hoist per (gaussian, row): arg(y) = e0 + e1*y + D*y^2
        float dx = x - mx;
        float t  = A * dx;
        float c1 = B * dx;
        float c0 = fmaf(t, dx, Dm2);
        float e1 = c1 + Dm;
        float e0 = fmaf(nmy, c1, c0);

        // v0 = 2^(arg at y0); r0 = v1/v0 = 2^(delta*(e1 + D*(2*y0+delta)))
        float arg0 = fmaf(e1, y0, fmaf(D, y0sq, e0));
        float rarg = inv * fmaf(D, c2y0d, e1);
        float v0 = ex2f(arg0);
        float r0 = ex2f(rarg);

        float v1  = v0 * r0;
        float r0q = r0 * r0;
        u64 V  = pk2(v0, v1);
        u64 P  = mul2(pk2(r0q, r0q), pk2(q2.x, q2.y));   // {r0^2*s, r0^2*s^3}
        u64 S4 = pk2(s4, s4);

        u64 wr2 = pk2(q2.z, q2.z);
        u64 wg2 = pk2(q2.w, q2.w);
        u64 wb2 = pk2(wb, wb);

        #pragma unroll
        for (int kk = 0; kk < TPX / 2; kk++) {
            ar2[kk] = fma2(V, wr2, ar2[kk]);
            ag2[kk] = fma2(V, wg2, ag2[kk]);
            ab2[kk] = fma2(V, wb2, ab2[kk]);
            if (kk < TPX / 2 - 1) {
                V = mul2(V, P);
                if (kk < TPX / 2 - 2) P = mul2(P, S4);
            }
        }
    }

    // Unpack and store: 96 contiguous floats per thread -> 24 x STG.128
    #pragma unroll
    for (int half = 0; half < 2; half++) {
        float r[TPX / 2], g[TPX / 2], b[TPX / 2];
        #pragma unroll
        for (int kk = 0; kk < TPX / 4; kk++) {
            int src = half * (TPX / 4) + kk;
            upk2(ar2[src], r[2 * kk], r[2 * kk + 1]);
            upk2(ag2[src], g[2 * kk], g[2 * kk + 1]);
            upk2(ab2[src], b[2 * kk], b[2 * kk + 1]);
        }
        float buf[TPX / 2 * 3];
        #pragma unroll
        for (int j = 0; j < TPX / 2; j++) {
            buf[3 * j + 0] = r[j];
            buf[3 * j + 1] = g[j];
            buf[3 * j + 2] = b[j];
        }
        float4* o = (float4*)(out + ((size_t)h * WW + w0 + half * (TPX / 2)) * 3);
        #pragma unroll
        for (int qq = 0; qq < TPX / 2 * 3 / 4; qq++) o[qq] = ((float4*)buf)[qq];
    }
}

extern "C" void kernel_launch(void* const* d_in, const int* in_sizes, int n_in,
                              void* d_out, int out_size) {
    const float* means  = (const float*)d_in[0];
    const float* cov    = (const float*)d_in[1];
    const float* colors = (const float*)d_in[2];
    float* out = (float*)d_out;

    static int configured = 0;
    if (!configured) {
        cudaFuncSetAttribute(render_kernel,
                             cudaFuncAttributeMaxDynamicSharedMemorySize, NG * 16 * 4);
        configured = 1;
    }

    prep_kernel<<<4, 256>>>(means, cov, colors);
    dim3 grid(WW / 128, HH / 16);
    render_kernel<<<grid, 64, NG * 16 * 4>>>(out);
}